// round 10
// baseline (speedup 1.0000x reference)
#include <cuda_runtime.h>
#include <cuda_bf16.h>
#include <cstdint>
#include <cstddef>
#include <cstring>

// ---------------- problem constants ----------------
#define NN       26
#define KDIM     676
#define KPAD     704          // 22 * 32
#define NCHUNK   22
#define HID      256

// GAT output as bf16 hi/lo split [B, KPAD]
__device__ __nv_bfloat16 g_Ahi[16384 * KPAD];
__device__ __nv_bfloat16 g_Alo[16384 * KPAD];
// W1^T split: [256 n][KPAD k]
__device__ __nv_bfloat16 g_Bhi[256 * KPAD];
__device__ __nv_bfloat16 g_Blo[256 * KPAD];
// GAT weights, augmented-K layout: [12 lh][32 o][80 c]:
//   cols 0-25 = W_hi(f), 26-51 = W_hi(f), 52-77 = W_lo(f), 78-79 = 0
__device__ __nv_bfloat16 g_Wa[12 * 32 * 80];
// score vectors wsrc/wdst = W @ a_*: [12 lh][32 f]
__device__ float g_wsrc[12 * 32];
__device__ float g_wdst[12 * 32];

// ---------------- common helpers ----------------
__device__ __forceinline__ uint32_t smem_u32(const void* p) {
    uint32_t a;
    asm("{ .reg .u64 t; cvta.to.shared.u64 t, %1; cvt.u32.u64 %0, t; }" : "=r"(a) : "l"(p));
    return a;
}
__device__ __forceinline__ void ldsm4(uint32_t* d, uint32_t addr) {
    asm volatile("ldmatrix.sync.aligned.m8n8.x4.shared.b16 {%0,%1,%2,%3}, [%4];"
                 : "=r"(d[0]), "=r"(d[1]), "=r"(d[2]), "=r"(d[3]) : "r"(addr));
}
__device__ __forceinline__ void mma16816(float* c, const uint32_t* a, uint32_t b0, uint32_t b1) {
    asm volatile(
        "mma.sync.aligned.m16n8k16.row.col.f32.bf16.bf16.f32 "
        "{%0,%1,%2,%3}, {%4,%5,%6,%7}, {%8,%9}, {%0,%1,%2,%3};"
        : "+f"(c[0]), "+f"(c[1]), "+f"(c[2]), "+f"(c[3])
        : "r"(a[0]), "r"(a[1]), "r"(a[2]), "r"(a[3]), "r"(b0), "r"(b1));
}
__device__ __forceinline__ void cp16(uint32_t dst, const void* src) {
    asm volatile("cp.async.ca.shared.global [%0], [%1], 16;" :: "r"(dst), "l"(src) : "memory");
}
#define CP_COMMIT() asm volatile("cp.async.commit_group;" ::: "memory")
#define CP_WAIT1()  asm volatile("cp.async.wait_group 1;" ::: "memory")
#define CP_WAIT0()  asm volatile("cp.async.wait_group 0;" ::: "memory")

// split two floats into packed bf16x2 hi + lo correction
__device__ __forceinline__ void split2(float a, float b, uint32_t& hi, uint32_t& lo) {
    __nv_bfloat162 h = __floats2bfloat162_rn(a, b);
    float ra = a - __bfloat162float(h.x);
    float rb = b - __bfloat162float(h.y);
    __nv_bfloat162 l = __floats2bfloat162_rn(ra, rb);
    memcpy(&hi, &h, 4);
    memcpy(&lo, &l, 4);
}
__device__ __forceinline__ float actelu(float v) {
    return v > 0.f ? v : (__expf(v) - 1.f);
}
__device__ __forceinline__ void sts32(uint32_t addr, uint32_t v) {
    asm volatile("st.shared.b32 [%0], %1;" :: "r"(addr), "r"(v) : "memory");
}
__device__ __forceinline__ void sts16(uint32_t addr, uint16_t v) {
    asm volatile("st.shared.b16 [%0], %1;" :: "r"(addr), "h"(v) : "memory");
}

// =====================================================================
// merged prep kernel
// =====================================================================
__global__ void prep_all(const float* __restrict__ W1,
                         const float* __restrict__ W,
                         const float* __restrict__ a_src,
                         const float* __restrict__ a_dst)
{
    int i = blockIdx.x * 256 + threadIdx.x;
    if (i < 256 * KPAD) {
        int n = i / KPAD, k = i % KPAD;
        float v = (k < KDIM) ? W1[(size_t)k * HID + n] : 0.f;
        __nv_bfloat16 h = __float2bfloat16_rn(v);
        g_Bhi[i] = h;
        g_Blo[i] = __float2bfloat16_rn(v - __bfloat162float(h));
        return;
    }
    int u = i - 256 * KPAD;
    if (u < 12 * 32 * 80) {
        int lh = u / 2560, r = u % 2560, o = r / 80, c = r % 80;
        __nv_bfloat16 res = __float2bfloat16_rn(0.f);
        if (o < 26 && c < 78) {
            int seg = (c < 26) ? 0 : ((c < 52) ? 1 : 2);
            int f = c - seg * 26;
            float v = W[((size_t)lh * 26 + f) * 26 + o];
            __nv_bfloat16 h = __float2bfloat16_rn(v);
            if (seg < 2) res = h;
            else         res = __float2bfloat16_rn(v - __bfloat162float(h));
        }
        g_Wa[u] = res;
        return;
    }
    int j = u - 12 * 32 * 80;
    if (j < 12 * 32) {
        int lh = j / 32, f = j % 32;
        float s = 0.f, d = 0.f;
        if (f < 26) {
            for (int o = 0; o < 26; o++) {
                float wv = W[((size_t)lh * 26 + f) * 26 + o];
                s = fmaf(wv, a_src[lh * 26 + o], s);
                d = fmaf(wv, a_dst[lh * 26 + o], d);
            }
        }
        g_wsrc[j] = s;
        g_wdst[j] = d;
    }
}

// =====================================================================
// GAT, augmented-K 3-term split: one GEMM per step (5 k16 tiles instead
// of 3 products x 2 tiles). warp = element, 8 warps/block.
// smem layouts (all rows 160 B = 80 bf16):
//   X_aug  [32 f][80]: cols 0-25 X_hi(j), 26-51 X_hi(j), 52-77 X_lo(j)
//   AY     [32 i][80]: alpha [E_hi,E_lo,E_hi] then aliased by
//                      Y     [Y_hi,Y_lo,Y_hi]   (alpha dead after step1)
//   W_aug  [4 h][32 o][80]: [W_hi,W_hi,W_lo]
// =====================================================================
#define XA   0                 // 8 * 5120 = 40960
#define AY   40960             // 8 * 5120 = 40960
#define WA   81920             // 20480
#define SDST 102400            // 8 * 128 floats = 4096
#define SWS  106496            // 512
#define SWD  107008            // 512
#define GAT_SMEM 107520

// two-pass softmax for one head; writes unnormalized exp (aug layout) to
// alpha; returns inv for rows g, g+8, 16+g, 24+g via shuffles.
__device__ __forceinline__ void softmax_head(
    float sh, const float* sdsth, uint32_t ayA, int lane,
    float& ia, float& ib, float& ic, float& id)
{
    float m = -1e30f;
    #pragma unroll
    for (int j = 0; j < 26; j++) {
        float v = sh + sdsth[j];
        v = fmaxf(v, 0.2f * v);
        m = fmaxf(m, v);
    }
    float su = 0.f;
    const uint32_t rowA = ayA + (uint32_t)lane * 160;
    #pragma unroll
    for (int jj = 0; jj < 13; jj++) {
        float v0 = sh + sdsth[2 * jj];     v0 = fmaxf(v0, 0.2f * v0);
        float v1 = sh + sdsth[2 * jj + 1]; v1 = fmaxf(v1, 0.2f * v1);
        float p0 = __expf(v0 - m), p1 = __expf(v1 - m);
        su += p0 + p1;
        uint32_t hi, lo;
        split2(p0, p1, hi, lo);
        sts32(rowA + 4 * jj, hi);          // seg0: E_hi
        sts32(rowA + 52 + 4 * jj, lo);     // seg1: E_lo
        sts32(rowA + 104 + 4 * jj, hi);    // seg2: E_hi dup
    }
    float inv = 1.f / su;
    int g = lane >> 2;
    ia = __shfl_sync(0xffffffffu, inv, g);
    ib = __shfl_sync(0xffffffffu, inv, g + 8);
    ic = __shfl_sync(0xffffffffu, inv, g + 16);
    id = __shfl_sync(0xffffffffu, inv, g + 24);
}

__global__ __launch_bounds__(256, 2)
void gat_tc(const float* __restrict__ x)
{
    extern __shared__ char sm[];
    const uint32_t sb = smem_u32(sm);
    const int tid = threadIdx.x, w = tid >> 5, lane = tid & 31;
    const int b = blockIdx.x * 8 + w;
    const int g = lane >> 2, tc2 = (lane & 3) * 2;

    // zero X_aug and AY regions once (pads stay zero)
    {
        uint4* p = (uint4*)(sm + XA);
        for (int i = tid; i < 81920 / 16; i += 256)
            p[i] = make_uint4(0, 0, 0, 0);
    }
    __syncthreads();

    __nv_bfloat16* xa = (__nv_bfloat16*)(sm + XA) + w * 2560;   // [32 f][80]
    float* sdst = (float*)(sm + SDST) + w * 128;                // [4 h][32 j]
    float* sws  = (float*)(sm + SWS);
    float* swd  = (float*)(sm + SWD);

    const uint32_t xaA = sb + XA + w * 5120;
    const uint32_t ayA = sb + AY + w * 5120;

    // stage x (layer 0): X_aug = [X_hi, X_hi, X_lo]
    for (int idx = lane; idx < KDIM; idx += 32) {
        int i = idx / 26, f = idx % 26;
        float v = x[(size_t)b * KDIM + idx];
        __nv_bfloat16 h = __float2bfloat16_rn(v);
        __nv_bfloat16 lo = __float2bfloat16_rn(v - __bfloat162float(h));
        xa[f * 80 + i]      = h;
        xa[f * 80 + 26 + i] = h;
        xa[f * 80 + 52 + i] = lo;
    }

    const int rpat = lane & 15;
    const int chalf = (lane >> 4) * 8;

    for (int l = 0; l < 3; l++) {
        __syncthreads();   // X writes done; W buffer free
        {
            const uint4* s0 = (const uint4*)(g_Wa + l * 10240);
            uint4* d0 = (uint4*)(sm + WA);
            for (int i = tid; i < 1280; i += 256) d0[i] = s0[i];
            if (tid < 128) {
                ((float*)(sm + SWS))[tid] = g_wsrc[l * 128 + tid];
                ((float*)(sm + SWD))[tid] = g_wdst[l * 128 + tid];
            }
        }
        __syncthreads();

        // ---- scores: lane = node index ----
        float ssrc[4];
        {
            float xi[26];
            #pragma unroll
            for (int f = 0; f < 26; f++)
                xi[f] = __bfloat162float(xa[f * 80 + lane]) +
                        __bfloat162float(xa[f * 80 + 52 + lane]);
            #pragma unroll
            for (int h = 0; h < 4; h++) {
                float s = 0.f, d = 0.f;
                #pragma unroll
                for (int f = 0; f < 26; f++) {
                    s = fmaf(xi[f], sws[h * 32 + f], s);
                    d = fmaf(xi[f], swd[h * 32 + f], d);
                }
                ssrc[h] = s;
                sdst[h * 32 + lane] = d;
            }
        }
        __syncwarp();

        float outf[2][4][4];
        #pragma unroll
        for (int mt = 0; mt < 2; mt++)
            #pragma unroll
            for (int nt = 0; nt < 4; nt++)
                #pragma unroll
                for (int q = 0; q < 4; q++) outf[mt][nt][q] = 0.f;

        for (int h = 0; h < 4; h++) {
            // ---- softmax (unnormalized) -> alpha_aug ----
            float ia, ib, ic, id;
            softmax_head(ssrc[h], sdst + h * 32, ayA, lane, ia, ib, ic, id);
            __syncwarp();

            // ---- step 1: Y = E_aug @ X_aug  (single GEMM, 5 k-tiles) ----
            float Yf[2][4][4];
            #pragma unroll
            for (int mt = 0; mt < 2; mt++)
                #pragma unroll
                for (int nt = 0; nt < 4; nt++)
                    #pragma unroll
                    for (int q = 0; q < 4; q++) Yf[mt][nt][q] = 0.f;

            #pragma unroll
            for (int ks = 0; ks < 5; ks++) {
                uint32_t Af[2][4], Xf[2][4];
                const uint32_t cb = (uint32_t)(ks * 16 + chalf) * 2;
                #pragma unroll
                for (int mt = 0; mt < 2; mt++)
                    ldsm4(Af[mt], ayA + (uint32_t)(mt * 16 + rpat) * 160 + cb);
                #pragma unroll
                for (int nt = 0; nt < 2; nt++)
                    ldsm4(Xf[nt], xaA + (uint32_t)(nt * 16 + rpat) * 160 + cb);
                #pragma unroll
                for (int mt = 0; mt < 2; mt++)
                    #pragma unroll
                    for (int nt = 0; nt < 2; nt++) {
                        mma16816(Yf[mt][nt * 2],     Af[mt], Xf[nt][0], Xf[nt][2]);
                        mma16816(Yf[mt][nt * 2 + 1], Af[mt], Xf[nt][1], Xf[nt][3]);
                    }
            }

            // ---- write Y_aug (1/sum folded): [Y_hi, Y_lo, Y_hi] ----
            // aliases alpha buffer (alpha fully consumed by step-1 ldsm)
            #pragma unroll
            for (int mt = 0; mt < 2; mt++) {
                const float va = (mt == 0) ? ia : ic;
                const float vb = (mt == 0) ? ib : id;
                const uint32_t r0 = ayA + (uint32_t)(mt * 16 + g) * 160;
                const uint32_t r1 = r0 + 8 * 160;
                #pragma unroll
                for (int j4 = 0; j4 < 4; j4++) {
                    const int f = j4 * 8 + tc2;
                    if (f < 26) {
                        uint32_t hi0, lo0, hi1, lo1;
                        split2(Yf[mt][j4][0] * va, Yf[mt][j4][1] * va, hi0, lo0);
                        split2(Yf[mt][j4][2] * vb, Yf[mt][j4][3] * vb, hi1, lo1);
                        sts32(r0 + 2 * f, hi0);
                        sts32(r0 + 52 + 2 * f, lo0);
                        sts32(r0 + 104 + 2 * f, hi0);
                        sts32(r1 + 2 * f, hi1);
                        sts32(r1 + 52 + 2 * f, lo1);
                        sts32(r1 + 104 + 2 * f, hi1);
                    }
                }
            }
            __syncwarp();

            // ---- step 2: out += Y_aug @ W_aug (5 k-tiles) ----
            #pragma unroll
            for (int ks = 0; ks < 5; ks++) {
                uint32_t Yt[2][4], Wf[2][4];
                const uint32_t cb = (uint32_t)(ks * 16 + chalf) * 2;
                #pragma unroll
                for (int mt = 0; mt < 2; mt++)
                    ldsm4(Yt[mt], ayA + (uint32_t)(mt * 16 + rpat) * 160 + cb);
                #pragma unroll
                for (int ot = 0; ot < 2; ot++)
                    ldsm4(Wf[ot], sb + WA + h * 5120 +
                                  (uint32_t)(ot * 16 + rpat) * 160 + cb);
                #pragma unroll
                for (int mt = 0; mt < 2; mt++)
                    #pragma unroll
                    for (int ot = 0; ot < 2; ot++) {
                        mma16816(outf[mt][ot * 2],     Yt[mt], Wf[ot][0], Wf[ot][2]);
                        mma16816(outf[mt][ot * 2 + 1], Yt[mt], Wf[ot][1], Wf[ot][3]);
                    }
            }
        } // heads

        // ---- epilogue: mean + ELU -> next X_aug or final global split ----
        if (l < 2) {
            __syncwarp();   // step-2 ldsm of X (scores) long done; X free
            #pragma unroll
            for (int mt = 0; mt < 2; mt++)
                #pragma unroll
                for (int nt = 0; nt < 4; nt++) {
                    int o = nt * 8 + tc2;
                    if (o < 26) {
                        #pragma unroll
                        for (int hf = 0; hf < 2; hf++) {
                            int j = mt * 16 + g + hf * 8;   // node index
                            if (j < 26) {
                                float v0 = actelu(outf[mt][nt][hf * 2]     * 0.25f);
                                float v1 = actelu(outf[mt][nt][hf * 2 + 1] * 0.25f);
                                __nv_bfloat16 h0 = __float2bfloat16_rn(v0);
                                __nv_bfloat16 l0 = __float2bfloat16_rn(v0 - __bfloat162float(h0));
                                __nv_bfloat16 h1 = __float2bfloat16_rn(v1);
                                __nv_bfloat16 l1 = __float2bfloat16_rn(v1 - __bfloat162float(h1));
                                uint16_t u;
                                memcpy(&u, &h0, 2);
                                sts16(xaA + (uint32_t)o * 160 + 2 * j, u);
                                sts16(xaA + (uint32_t)o * 160 + 52 + 2 * j, u);
                                memcpy(&u, &l0, 2);
                                sts16(xaA + (uint32_t)o * 160 + 104 + 2 * j, u);
                                memcpy(&u, &h1, 2);
                                sts16(xaA + (uint32_t)(o + 1) * 160 + 2 * j, u);
                                sts16(xaA + (uint32_t)(o + 1) * 160 + 52 + 2 * j, u);
                                memcpy(&u, &l1, 2);
                                sts16(xaA + (uint32_t)(o + 1) * 160 + 104 + 2 * j, u);
                            }
                        }
                    }
                }
        } else {
            #pragma unroll
            for (int mt = 0; mt < 2; mt++)
                #pragma unroll
                for (int nt = 0; nt < 4; nt++) {
                    int col = nt * 8 + tc2;
                    if (col < 26) {
                        #pragma unroll
                        for (int hf = 0; hf < 2; hf++) {
                            int row = mt * 16 + g + hf * 8;
                            if (row < 26) {
                                float v0 = actelu(outf[mt][nt][hf * 2]     * 0.25f);
                                float v1 = actelu(outf[mt][nt][hf * 2 + 1] * 0.25f);
                                uint32_t hi, lo;
                                split2(v0, v1, hi, lo);
                                size_t o = (size_t)b * KPAD + row * 26 + col;
                                *(uint32_t*)&g_Ahi[o] = hi;
                                *(uint32_t*)&g_Alo[o] = lo;
                            }
                        }
                    }
                }
            if (lane < 28) {
                g_Ahi[(size_t)b * KPAD + KDIM + lane] = __float2bfloat16_rn(0.f);
                g_Alo[(size_t)b * KPAD + KDIM + lane] = __float2bfloat16_rn(0.f);
            }
        }
    } // layers
}

// =====================================================================
// MLP via mma.sync bf16 (3-term split), hoisted loads — unchanged (R8).
// =====================================================================
#define STAGE_BYTES 51200
#define MLP_SMEM (2 * STAGE_BYTES)

__device__ __forceinline__ void copy_chunk(uint32_t smbase, int stage, int chunk,
                                           int row0, int tid)
{
    const uint32_t sbs = smbase + stage * STAGE_BYTES;
    #pragma unroll
    for (int k = 0; k < 10; k++) {
        int u = tid + k * 256;
        if (u < 512) {
            int t = u >> 8, r = (u & 255) >> 2, seg = u & 3;
            const __nv_bfloat16* base = t ? g_Alo : g_Ahi;
            const __nv_bfloat16* src = base + (size_t)(row0 + r) * KPAD + chunk * 32 + seg * 8;
            cp16(sbs + t * 5120 + r * 80 + seg * 16, src);
        } else {
            int v = u - 512;
            int t = v >> 10, r = (v & 1023) >> 2, seg = v & 3;
            const __nv_bfloat16* base = t ? g_Blo : g_Bhi;
            const __nv_bfloat16* src = base + (size_t)r * KPAD + chunk * 32 + seg * 8;
            cp16(sbs + 10240 + t * 20480 + r * 80 + seg * 16, src);
        }
    }
}

__global__ __launch_bounds__(256, 2)
void mlp_mma(const float* __restrict__ b1,
             const float* __restrict__ W2,
             const float* __restrict__ b2,
             float* __restrict__ out)
{
    extern __shared__ __align__(16) char dsm[];
    __shared__ float sb1[HID];
    __shared__ float sW2[HID * 3];
    __shared__ float sb2s[3];
    __shared__ float red[64][13];

    const int tid = threadIdx.x, wid = tid >> 5, lane = tid & 31;
    const int warp_m = wid & 1;
    const int warp_n = wid >> 1;
    const int row0 = blockIdx.x * 64;

    if (tid < HID) sb1[tid] = b1[tid];
    for (int i = tid; i < HID * 3; i += 256) sW2[i] = W2[i];
    if (tid < 3) sb2s[tid] = b2[tid];

    const uint32_t smbase = smem_u32(dsm);

    float acc[2][8][4];
    #pragma unroll
    for (int mt = 0; mt < 2; mt++)
        #pragma unroll
        for (int nt = 0; nt < 8; nt++)
            #pragma unroll
            for (int q = 0; q < 4; q++) acc[mt][nt][q] = 0.f;

    copy_chunk(smbase, 0, 0, row0, tid);
    CP_COMMIT();

    const int rpat = lane & 15;

    for (int c = 0; c < NCHUNK; c++) {
        const int s = c & 1;
        if (c + 1 < NCHUNK) {
            copy_chunk(smbase, s ^ 1, c + 1, row0, tid);
            CP_COMMIT();
            CP_WAIT1();
        } else {
            CP_WAIT0();
        }
        __syncthreads();

        const uint32_t stB = smbase + s * STAGE_BYTES;
        #pragma unroll
        for (int ks = 0; ks < 2; ks++) {
            const int cpat = ks * 16 + (lane >> 4) * 8;

            uint32_t ah[2][4], al[2][4], bh[4][4], bl[4][4];
            #pragma unroll
            for (int mt = 0; mt < 2; mt++) {
                const uint32_t a_off =
                    (uint32_t)((warp_m * 32 + mt * 16 + rpat) * 80 + cpat * 2);
                ldsm4(ah[mt], stB + a_off);
                ldsm4(al[mt], stB + 5120 + a_off);
            }
            #pragma unroll
            for (int np = 0; np < 4; np++) {
                const uint32_t b_off =
                    (uint32_t)((warp_n * 64 + np * 16 + rpat) * 80 + cpat * 2);
                ldsm4(bh[np], stB + 10240 + b_off);
                ldsm4(bl[np], stB + 30720 + b_off);
            }

            #pragma unroll
            for (int mt = 0; mt < 2; mt++)
                #pragma unroll
                for (int np = 0; np < 4; np++) {
                    mma16816(acc[mt][np * 2 + 0], ah[mt], bh[np][0], bh[np][2]);
                    mma16816(acc[mt][np * 2 + 1], ah[mt], bh[np][1], bh[np][3]);
                    mma16816(acc[mt][np * 2 + 0], al[mt], bh[np][0], bh[np][2]);
                    mma16816(acc[mt][np * 2 + 1], al[mt], bh[np][1], bh[np][3]);
                    mma16816(acc[mt][np * 2 + 0], ah[mt], bl[np][0], bl[np][2]);
                    mma16816(acc[mt][np * 2 + 1], ah[mt], bl[np][1], bl[np][3]);
                }
        }
        __syncthreads();
    }

    #pragma unroll
    for (int mt = 0; mt < 2; mt++) {
        #pragma unroll
        for (int half = 0; half < 2; half++) {
            float s0 = 0.f, s1 = 0.f, s2 = 0.f;
            #pragma unroll
            for (int nt = 0; nt < 8; nt++) {
                const int col = warp_n * 64 + nt * 8 + (lane & 3) * 2;
                float v0 = acc[mt][nt][half * 2 + 0] + sb1[col];
                v0 = fmaxf(v0, 0.2f * v0);
                float v1 = acc[mt][nt][half * 2 + 1] + sb1[col + 1];
                v1 = fmaxf(v1, 0.2f * v1);
                s0 += v0 * sW2[col * 3 + 0] + v1 * sW2[(col + 1) * 3 + 0];
                s1 += v0 * sW2[col * 3 + 1] + v1 * sW2[(col + 1) * 3 + 1];
                s2 += v0 * sW2[col * 3 + 2] + v1 * sW2[(col + 1) * 3 + 2];
            }
            s0 += __shfl_xor_sync(0xffffffffu, s0, 1);
            s0 += __shfl_xor_sync(0xffffffffu, s0, 2);
            s1 += __shfl_xor_sync(0xffffffffu, s1, 1);
            s1 += __shfl_xor_sync(0xffffffffu, s1, 2);
            s2 += __shfl_xor_sync(0xffffffffu, s2, 1);
            s2 += __shfl_xor_sync(0xffffffffu, s2, 2);
            if ((lane & 3) == 0) {
                const int row = warp_m * 32 + mt * 16 + half * 8 + (lane >> 2);
                red[row][warp_n * 3 + 0] = s0;
                red[row][warp_n * 3 + 1] = s1;
                red[row][warp_n * 3 + 2] = s2;
            }
        }
    }
    __syncthreads();
    if (tid < 64) {
        const int row = tid;
        #pragma unroll
        for (int oc = 0; oc < 3; oc++) {
            float v = red[row][oc] + red[row][3 + oc] + red[row][6 + oc] +
                      red[row][9 + oc] + sb2s[oc];
            out[(size_t)(row0 + row) * 3 + oc] = v;
        }
    }
}

// =====================================================================
// launch
// =====================================================================
extern "C" void kernel_launch(void* const* d_in, const int* in_sizes, int n_in,
                              void* d_out, int out_size)
{
    const float* x     = (const float*)d_in[1];
    const float* W     = (const float*)d_in[2];
    const float* a_src = (const float*)d_in[3];
    const float* a_dst = (const float*)d_in[4];
    const float* W1    = (const float*)d_in[5];
    const float* b1    = (const float*)d_in[6];
    const float* W2    = (const float*)d_in[7];
    const float* b2    = (const float*)d_in[8];
    float* out = (float*)d_out;

    const int batch = in_sizes[1] / KDIM;   // 16384

    cudaFuncSetAttribute(gat_tc, cudaFuncAttributeMaxDynamicSharedMemorySize, GAT_SMEM);
    cudaFuncSetAttribute(mlp_mma, cudaFuncAttributeMaxDynamicSharedMemorySize, MLP_SMEM);

    const int prep_total = 256 * KPAD + 12 * 32 * 80 + 12 * 32;
    prep_all<<<(prep_total + 255) / 256, 256>>>(W1, W, a_src, a_dst);
    gat_tc<<<batch / 8, 256, GAT_SMEM>>>(x);
    mlp_mma<<<batch / 64, 256, MLP_SMEM>>>(b1, W2, b2, out);
    (void)n_in; (void)out_size;
}

// round 11
// speedup vs baseline: 1.6355x; 1.6355x over previous
#include <cuda_runtime.h>
#include <cuda_bf16.h>
#include <cstdint>
#include <cstddef>
#include <cstring>

// ---------------- problem constants ----------------
#define NN       26
#define KDIM     676
#define KPAD     704          // 22 * 32
#define NCHUNK   22
#define HID      256

// GAT output as bf16 hi/lo split [B, KPAD]
__device__ __nv_bfloat16 g_Ahi[16384 * KPAD];
__device__ __nv_bfloat16 g_Alo[16384 * KPAD];
// W1^T split: [256 n][KPAD k]
__device__ __nv_bfloat16 g_Bhi[256 * KPAD];
__device__ __nv_bfloat16 g_Blo[256 * KPAD];
// GAT weights, transposed + padded + split: [12 lh][32 o][40 f]
__device__ __nv_bfloat16 g_Wth[12 * 32 * 40];
__device__ __nv_bfloat16 g_Wtl[12 * 32 * 40];
// score vectors wsrc/wdst = W @ a_*: [12 lh][32 f]
__device__ float g_wsrc[12 * 32];
__device__ float g_wdst[12 * 32];

// ---------------- common helpers ----------------
__device__ __forceinline__ uint32_t smem_u32(const void* p) {
    uint32_t a;
    asm("{ .reg .u64 t; cvta.to.shared.u64 t, %1; cvt.u32.u64 %0, t; }" : "=r"(a) : "l"(p));
    return a;
}
__device__ __forceinline__ void ldsm4(uint32_t* d, uint32_t addr) {
    asm volatile("ldmatrix.sync.aligned.m8n8.x4.shared.b16 {%0,%1,%2,%3}, [%4];"
                 : "=r"(d[0]), "=r"(d[1]), "=r"(d[2]), "=r"(d[3]) : "r"(addr));
}
__device__ __forceinline__ void mma16816(float* c, const uint32_t* a, uint32_t b0, uint32_t b1) {
    asm volatile(
        "mma.sync.aligned.m16n8k16.row.col.f32.bf16.bf16.f32 "
        "{%0,%1,%2,%3}, {%4,%5,%6,%7}, {%8,%9}, {%0,%1,%2,%3};"
        : "+f"(c[0]), "+f"(c[1]), "+f"(c[2]), "+f"(c[3])
        : "r"(a[0]), "r"(a[1]), "r"(a[2]), "r"(a[3]), "r"(b0), "r"(b1));
}
__device__ __forceinline__ void cp16(uint32_t dst, const void* src) {
    asm volatile("cp.async.ca.shared.global [%0], [%1], 16;" :: "r"(dst), "l"(src) : "memory");
}
#define CP_COMMIT() asm volatile("cp.async.commit_group;" ::: "memory")
#define CP_WAIT1()  asm volatile("cp.async.wait_group 1;" ::: "memory")
#define CP_WAIT0()  asm volatile("cp.async.wait_group 0;" ::: "memory")

// split two floats into packed bf16x2 hi + lo correction
__device__ __forceinline__ void split2(float a, float b, uint32_t& hi, uint32_t& lo) {
    __nv_bfloat162 h = __floats2bfloat162_rn(a, b);
    float ra = a - __bfloat162float(h.x);
    float rb = b - __bfloat162float(h.y);
    __nv_bfloat162 l = __floats2bfloat162_rn(ra, rb);
    memcpy(&hi, &h, 4);
    memcpy(&lo, &l, 4);
}
__device__ __forceinline__ float actelu(float v) {
    return v > 0.f ? v : (__expf(v) - 1.f);
}

// =====================================================================
// merged prep kernel
// =====================================================================
__global__ void prep_all(const float* __restrict__ W1,
                         const float* __restrict__ W,
                         const float* __restrict__ a_src,
                         const float* __restrict__ a_dst)
{
    int i = blockIdx.x * 256 + threadIdx.x;
    if (i < 256 * KPAD) {
        int n = i / KPAD, k = i % KPAD;
        float v = (k < KDIM) ? W1[(size_t)k * HID + n] : 0.f;
        __nv_bfloat16 h = __float2bfloat16_rn(v);
        g_Bhi[i] = h;
        g_Blo[i] = __float2bfloat16_rn(v - __bfloat162float(h));
        return;
    }
    int u = i - 256 * KPAD;
    if (u < 12 * 32 * 40) {
        int lh = u / 1280, r = u % 1280, o = r / 40, f = r % 40;
        float v = (o < 26 && f < 26) ? W[((size_t)lh * 26 + f) * 26 + o] : 0.f;
        __nv_bfloat16 h = __float2bfloat16_rn(v);
        g_Wth[u] = h;
        g_Wtl[u] = __float2bfloat16_rn(v - __bfloat162float(h));
        return;
    }
    int j = u - 12 * 32 * 40;
    if (j < 12 * 32) {
        int lh = j / 32, f = j % 32;
        float s = 0.f, d = 0.f;
        if (f < 26) {
            for (int o = 0; o < 26; o++) {
                float wv = W[((size_t)lh * 26 + f) * 26 + o];
                s = fmaf(wv, a_src[lh * 26 + o], s);
                d = fmaf(wv, a_dst[lh * 26 + o], d);
            }
        }
        g_wsrc[j] = s;
        g_wdst[j] = d;
    }
}

// zero-init d_out (poisoned by harness; mlp uses atomicAdd)
__global__ void zero_out(float* __restrict__ out, int n)
{
    int i = blockIdx.x * 256 + threadIdx.x;
    if (i < n) out[i] = 0.f;
}

// =====================================================================
// GAT on tensor cores — byte-identical to the 431.4us R8 kernel.
// =====================================================================
#define XTH 0
#define XTL 20480
#define APH 40960
#define APL 61440
#define WTH 81920
#define WTL 92160
#define SDST 102400
#define SWS 106496
#define SWD 107008
#define GAT_SMEM 107520

__global__ __launch_bounds__(256, 2)
void gat_tc(const float* __restrict__ x)
{
    extern __shared__ char sm[];
    const uint32_t sb = smem_u32(sm);
    const int tid = threadIdx.x, w = tid >> 5, lane = tid & 31;
    const int b = blockIdx.x * 8 + w;

    // zero xT buffers once (pads stay zero forever)
    {
        uint4* p = (uint4*)(sm + XTH);
        for (int i = tid; i < (20480 * 2) / 16; i += 256)
            p[i] = make_uint4(0, 0, 0, 0);
    }
    __syncthreads();

    __nv_bfloat16* xth = (__nv_bfloat16*)(sm + XTH) + w * 1280;   // [32 f][40 j]
    __nv_bfloat16* xtl = (__nv_bfloat16*)(sm + XTL) + w * 1280;
    __nv_bfloat16* aph = (__nv_bfloat16*)(sm + APH) + w * 1280;   // [32 i][40 j]
    __nv_bfloat16* apl = (__nv_bfloat16*)(sm + APL) + w * 1280;
    float* sdst = (float*)(sm + SDST) + w * 128;                  // [4 h][32 j]
    float* sws  = (float*)(sm + SWS);                             // [4 h][32 f]
    float* swd  = (float*)(sm + SWD);

    // stage x (layer 0): transposed bf16 split
    for (int idx = lane; idx < KDIM; idx += 32) {
        int i = idx / 26, f = idx % 26;
        float v = x[(size_t)b * KDIM + idx];
        __nv_bfloat16 h = __float2bfloat16_rn(v);
        xth[f * 40 + i] = h;
        xtl[f * 40 + i] = __float2bfloat16_rn(v - __bfloat162float(h));
    }

    const int rpat = lane & 15;
    const int chalf = (lane >> 4) * 8;
    const uint32_t xthA = sb + XTH + w * 2560;
    const uint32_t xtlA = sb + XTL + w * 2560;
    const uint32_t aphA = sb + APH + w * 2560;
    const uint32_t aplA = sb + APL + w * 2560;

    for (int l = 0; l < 3; l++) {
        __syncthreads();   // xT writes done; W buffer free
        {
            const uint4* s0 = (const uint4*)(g_Wth + l * 5120);
            const uint4* s1 = (const uint4*)(g_Wtl + l * 5120);
            uint4* d0 = (uint4*)(sm + WTH);
            uint4* d1 = (uint4*)(sm + WTL);
            for (int i = tid; i < 640; i += 256) { d0[i] = s0[i]; d1[i] = s1[i]; }
            if (tid < 128) {
                ((float*)(sm + SWS))[tid] = g_wsrc[l * 128 + tid];
                ((float*)(sm + SWD))[tid] = g_wdst[l * 128 + tid];
            }
        }
        __syncthreads();

        // ---- scores: lane = node index ----
        float ssrc[4];
        {
            float xi[26];
            #pragma unroll
            for (int f = 0; f < 26; f++)
                xi[f] = __bfloat162float(xth[f * 40 + lane]) +
                        __bfloat162float(xtl[f * 40 + lane]);
            #pragma unroll
            for (int h = 0; h < 4; h++) {
                float s = 0.f, d = 0.f;
                #pragma unroll
                for (int f = 0; f < 26; f++) {
                    s = fmaf(xi[f], sws[h * 32 + f], s);
                    d = fmaf(xi[f], swd[h * 32 + f], d);
                }
                ssrc[h] = s;
                sdst[h * 32 + lane] = d;
            }
        }
        __syncwarp();

        float outf[2][4][4];
        #pragma unroll
        for (int mt = 0; mt < 2; mt++)
            #pragma unroll
            for (int nt = 0; nt < 4; nt++)
                #pragma unroll
                for (int q = 0; q < 4; q++) outf[mt][nt][q] = 0.f;

        for (int h = 0; h < 4; h++) {
            // ---- softmax row (lane = i) ----
            float e[NN];
            float m = -1e30f;
            #pragma unroll
            for (int j = 0; j < NN; j++) {
                float v = ssrc[h] + sdst[h * 32 + j];
                v = fmaxf(v, 0.2f * v);
                e[j] = v;
                m = fmaxf(m, v);
            }
            float su = 0.f;
            #pragma unroll
            for (int j = 0; j < NN; j++) {
                float p = __expf(e[j] - m);
                e[j] = p;
                su += p;
            }
            const float inv = 1.0f / su;
            #pragma unroll
            for (int jj = 0; jj < 16; jj++) {
                float a0 = (2 * jj < 26) ? e[(2 * jj < 26) ? 2 * jj : 0] * inv : 0.f;
                float a1 = (2 * jj + 1 < 26) ? e[(2 * jj + 1 < 26) ? 2 * jj + 1 : 0] * inv : 0.f;
                uint32_t hi, lo;
                split2(a0, a1, hi, lo);
                *(uint32_t*)(aph + lane * 40 + 2 * jj) = hi;
                *(uint32_t*)(apl + lane * 40 + 2 * jj) = lo;
            }
            __syncwarp();

            // ---- step 1: Y = alpha @ x  (3-term split) ----
            float Yf[2][4][4];
            #pragma unroll
            for (int mt = 0; mt < 2; mt++)
                #pragma unroll
                for (int nt = 0; nt < 4; nt++)
                    #pragma unroll
                    for (int q = 0; q < 4; q++) Yf[mt][nt][q] = 0.f;

            #pragma unroll
            for (int ks = 0; ks < 2; ks++) {
                uint32_t Ah[2][4], Al[2][4], Xh[2][4], Xl[2][4];
                #pragma unroll
                for (int mt = 0; mt < 2; mt++) {
                    uint32_t off = (uint32_t)((mt * 16 + rpat) * 80 + (ks * 16 + chalf) * 2);
                    ldsm4(Ah[mt], aphA + off);
                    ldsm4(Al[mt], aplA + off);
                }
                #pragma unroll
                for (int nt = 0; nt < 2; nt++) {
                    uint32_t off = (uint32_t)((nt * 16 + rpat) * 80 + (ks * 16 + chalf) * 2);
                    ldsm4(Xh[nt], xthA + off);
                    ldsm4(Xl[nt], xtlA + off);
                }
                #pragma unroll
                for (int mt = 0; mt < 2; mt++)
                    #pragma unroll
                    for (int nt = 0; nt < 2; nt++) {
                        mma16816(Yf[mt][nt * 2],     Ah[mt], Xh[nt][0], Xh[nt][2]);
                        mma16816(Yf[mt][nt * 2 + 1], Ah[mt], Xh[nt][1], Xh[nt][3]);
                        mma16816(Yf[mt][nt * 2],     Ah[mt], Xl[nt][0], Xl[nt][2]);
                        mma16816(Yf[mt][nt * 2 + 1], Ah[mt], Xl[nt][1], Xl[nt][3]);
                        mma16816(Yf[mt][nt * 2],     Al[mt], Xh[nt][0], Xh[nt][2]);
                        mma16816(Yf[mt][nt * 2 + 1], Al[mt], Xh[nt][1], Xh[nt][3]);
                    }
            }

            // ---- in-register C -> A fragment conversion (split) ----
            uint32_t YAh[2][2][4], YAl[2][2][4];
            #pragma unroll
            for (int mt = 0; mt < 2; mt++)
                #pragma unroll
                for (int ks = 0; ks < 2; ks++) {
                    split2(Yf[mt][2 * ks][0],     Yf[mt][2 * ks][1],     YAh[mt][ks][0], YAl[mt][ks][0]);
                    split2(Yf[mt][2 * ks][2],     Yf[mt][2 * ks][3],     YAh[mt][ks][1], YAl[mt][ks][1]);
                    split2(Yf[mt][2 * ks + 1][0], Yf[mt][2 * ks + 1][1], YAh[mt][ks][2], YAl[mt][ks][2]);
                    split2(Yf[mt][2 * ks + 1][2], Yf[mt][2 * ks + 1][3], YAh[mt][ks][3], YAl[mt][ks][3]);
                }

            // ---- step 2: out += Y @ W_h ----
            #pragma unroll
            for (int ks = 0; ks < 2; ks++) {
                uint32_t Wh[2][4], Wl[2][4];
                #pragma unroll
                for (int ot = 0; ot < 2; ot++) {
                    uint32_t off = (uint32_t)((ot * 16 + rpat) * 80 + (ks * 16 + chalf) * 2);
                    ldsm4(Wh[ot], sb + WTH + h * 2560 + off);
                    ldsm4(Wl[ot], sb + WTL + h * 2560 + off);
                }
                #pragma unroll
                for (int mt = 0; mt < 2; mt++)
                    #pragma unroll
                    for (int ot = 0; ot < 2; ot++) {
                        mma16816(outf[mt][ot * 2],     YAh[mt][ks], Wh[ot][0], Wh[ot][2]);
                        mma16816(outf[mt][ot * 2 + 1], YAh[mt][ks], Wh[ot][1], Wh[ot][3]);
                        mma16816(outf[mt][ot * 2],     YAh[mt][ks], Wl[ot][0], Wl[ot][2]);
                        mma16816(outf[mt][ot * 2 + 1], YAh[mt][ks], Wl[ot][1], Wl[ot][3]);
                        mma16816(outf[mt][ot * 2],     YAl[mt][ks], Wh[ot][0], Wh[ot][2]);
                        mma16816(outf[mt][ot * 2 + 1], YAl[mt][ks], Wh[ot][1], Wh[ot][3]);
                    }
            }
        } // heads

        // ---- epilogue: mean + ELU, write next xT or final global split ----
        const int g = lane >> 2, tc2 = (lane & 3) * 2;
        if (l < 2) {
            #pragma unroll
            for (int mt = 0; mt < 2; mt++)
                #pragma unroll
                for (int nt = 0; nt < 4; nt++) {
                    int col = nt * 8 + tc2;
                    if (col < 26) {
                        #pragma unroll
                        for (int hf = 0; hf < 2; hf++) {
                            int row = mt * 16 + g + hf * 8;
                            if (row < 26) {
                                float v0 = actelu(outf[mt][nt][hf * 2]     * 0.25f);
                                float v1 = actelu(outf[mt][nt][hf * 2 + 1] * 0.25f);
                                __nv_bfloat16 h0 = __float2bfloat16_rn(v0);
                                __nv_bfloat16 h1 = __float2bfloat16_rn(v1);
                                xth[col * 40 + row] = h0;
                                xtl[col * 40 + row] = __float2bfloat16_rn(v0 - __bfloat162float(h0));
                                xth[(col + 1) * 40 + row] = h1;
                                xtl[(col + 1) * 40 + row] = __float2bfloat16_rn(v1 - __bfloat162float(h1));
                            }
                        }
                    }
                }
        } else {
            #pragma unroll
            for (int mt = 0; mt < 2; mt++)
                #pragma unroll
                for (int nt = 0; nt < 4; nt++) {
                    int col = nt * 8 + tc2;
                    if (col < 26) {
                        #pragma unroll
                        for (int hf = 0; hf < 2; hf++) {
                            int row = mt * 16 + g + hf * 8;
                            if (row < 26) {
                                float v0 = actelu(outf[mt][nt][hf * 2]     * 0.25f);
                                float v1 = actelu(outf[mt][nt][hf * 2 + 1] * 0.25f);
                                uint32_t hi, lo;
                                split2(v0, v1, hi, lo);
                                size_t o = (size_t)b * KPAD + row * 26 + col;
                                *(uint32_t*)&g_Ahi[o] = hi;
                                *(uint32_t*)&g_Alo[o] = lo;
                            }
                        }
                    }
                }
            if (lane < 28) {
                g_Ahi[(size_t)b * KPAD + KDIM + lane] = __float2bfloat16_rn(0.f);
                g_Alo[(size_t)b * KPAD + KDIM + lane] = __float2bfloat16_rn(0.f);
            }
        }
    } // layers
}

// =====================================================================
// MLP via mma.sync bf16 (3-term split), N-SPLIT: block = 64 rows x 128
// cols (blockIdx.y = col half). Stage 30.7KB -> 3 CTAs/SM (24 warps).
// Col halves combine via atomicAdd (2 commutative fp32 adds -> exact).
// =====================================================================
#define STAGE_BYTES 30720
#define MLP_SMEM (2 * STAGE_BYTES)

__device__ __forceinline__ void copy_chunk(uint32_t smbase, int stage, int chunk,
                                           int row0, int n0, int tid)
{
    const uint32_t sbs = smbase + stage * STAGE_BYTES;
    #pragma unroll
    for (int k = 0; k < 6; k++) {
        int u = tid + k * 256;
        if (u < 512) {
            int t = u >> 8, r = (u & 255) >> 2, seg = u & 3;
            const __nv_bfloat16* base = t ? g_Alo : g_Ahi;
            const __nv_bfloat16* src = base + (size_t)(row0 + r) * KPAD + chunk * 32 + seg * 8;
            cp16(sbs + t * 5120 + r * 80 + seg * 16, src);
        } else {
            int v = u - 512;
            int t = v >> 9, r = (v & 511) >> 2, seg = v & 3;
            const __nv_bfloat16* base = t ? g_Blo : g_Bhi;
            const __nv_bfloat16* src = base + (size_t)(n0 + r) * KPAD + chunk * 32 + seg * 8;
            cp16(sbs + 10240 + t * 10240 + r * 80 + seg * 16, src);
        }
    }
}

__global__ __launch_bounds__(256, 3)
void mlp_mma(const float* __restrict__ b1,
             const float* __restrict__ W2,
             const float* __restrict__ b2,
             float* __restrict__ out)
{
    extern __shared__ __align__(16) char dsm[];
    __shared__ float sb1[128];
    __shared__ float sW2[128 * 3];
    __shared__ float sb2s[3];
    __shared__ float red[64][12];

    const int tid = threadIdx.x, wid = tid >> 5, lane = tid & 31;
    const int warp_m = wid & 1;          // 0..1 -> 32-row half
    const int warp_n = wid >> 1;         // 0..3 -> 32-col slice
    const int row0 = blockIdx.x * 64;
    const int n0   = blockIdx.y * 128;   // hidden-col half

    if (tid < 128) sb1[tid] = b1[n0 + tid];
    for (int i = tid; i < 128 * 3; i += 256) sW2[i] = W2[n0 * 3 + i];
    if (tid < 3) sb2s[tid] = (blockIdx.y == 0) ? b2[tid] : 0.f;

    const uint32_t smbase = smem_u32(dsm);

    float acc[2][4][4];
    #pragma unroll
    for (int mt = 0; mt < 2; mt++)
        #pragma unroll
        for (int nt = 0; nt < 4; nt++)
            #pragma unroll
            for (int q = 0; q < 4; q++) acc[mt][nt][q] = 0.f;

    copy_chunk(smbase, 0, 0, row0, n0, tid);
    CP_COMMIT();

    const int rpat = lane & 15;

    for (int c = 0; c < NCHUNK; c++) {
        const int s = c & 1;
        if (c + 1 < NCHUNK) {
            copy_chunk(smbase, s ^ 1, c + 1, row0, n0, tid);
            CP_COMMIT();
            CP_WAIT1();
        } else {
            CP_WAIT0();
        }
        __syncthreads();

        const uint32_t stB = smbase + s * STAGE_BYTES;
        #pragma unroll
        for (int ks = 0; ks < 2; ks++) {
            const int cpat = ks * 16 + (lane >> 4) * 8;

            uint32_t ah[2][4], al[2][4], bh[2][4], bl[2][4];
            #pragma unroll
            for (int mt = 0; mt < 2; mt++) {
                const uint32_t a_off =
                    (uint32_t)((warp_m * 32 + mt * 16 + rpat) * 80 + cpat * 2);
                ldsm4(ah[mt], stB + a_off);
                ldsm4(al[mt], stB + 5120 + a_off);
            }
            #pragma unroll
            for (int np = 0; np < 2; np++) {
                const uint32_t b_off =
                    (uint32_t)((warp_n * 32 + np * 16 + rpat) * 80 + cpat * 2);
                ldsm4(bh[np], stB + 10240 + b_off);
                ldsm4(bl[np], stB + 20480 + b_off);
            }

            #pragma unroll
            for (int mt = 0; mt < 2; mt++)
                #pragma unroll
                for (int np = 0; np < 2; np++) {
                    mma16816(acc[mt][np * 2 + 0], ah[mt], bh[np][0], bh[np][2]);
                    mma16816(acc[mt][np * 2 + 1], ah[mt], bh[np][1], bh[np][3]);
                    mma16816(acc[mt][np * 2 + 0], al[mt], bh[np][0], bh[np][2]);
                    mma16816(acc[mt][np * 2 + 1], al[mt], bh[np][1], bh[np][3]);
                    mma16816(acc[mt][np * 2 + 0], ah[mt], bl[np][0], bl[np][2]);
                    mma16816(acc[mt][np * 2 + 1], ah[mt], bl[np][1], bl[np][3]);
                }
        }
        __syncthreads();
    }

    // ---- epilogue: bias + lrelu + partial W2, reduce, atomicAdd ----
    #pragma unroll
    for (int mt = 0; mt < 2; mt++) {
        #pragma unroll
        for (int half = 0; half < 2; half++) {
            float s0 = 0.f, s1 = 0.f, s2 = 0.f;
            #pragma unroll
            for (int nt = 0; nt < 4; nt++) {
                const int col = warp_n * 32 + nt * 8 + (lane & 3) * 2;
                float v0 = acc[mt][nt][half * 2 + 0] + sb1[col];
                v0 = fmaxf(v0, 0.2f * v0);
                float v1 = acc[mt][nt][half * 2 + 1] + sb1[col + 1];
                v1 = fmaxf(v1, 0.2f * v1);
                s0 += v0 * sW2[col * 3 + 0] + v1 * sW2[(col + 1) * 3 + 0];
                s1 += v0 * sW2[col * 3 + 1] + v1 * sW2[(col + 1) * 3 + 1];
                s2 += v0 * sW2[col * 3 + 2] + v1 * sW2[(col + 1) * 3 + 2];
            }
            s0 += __shfl_xor_sync(0xffffffffu, s0, 1);
            s0 += __shfl_xor_sync(0xffffffffu, s0, 2);
            s1 += __shfl_xor_sync(0xffffffffu, s1, 1);
            s1 += __shfl_xor_sync(0xffffffffu, s1, 2);
            s2 += __shfl_xor_sync(0xffffffffu, s2, 1);
            s2 += __shfl_xor_sync(0xffffffffu, s2, 2);
            if ((lane & 3) == 0) {
                const int row = warp_m * 32 + mt * 16 + half * 8 + (lane >> 2);
                red[row][warp_n * 3 + 0] = s0;
                red[row][warp_n * 3 + 1] = s1;
                red[row][warp_n * 3 + 2] = s2;
            }
        }
    }
    __syncthreads();
    if (tid < 64) {
        const int row = tid;
        #pragma unroll
        for (int oc = 0; oc < 3; oc++) {
            float v = red[row][oc] + red[row][3 + oc] + red[row][6 + oc] +
                      red[row][9 + oc] + sb2s[oc];
            atomicAdd(&out[(size_t)(row0 + row) * 3 + oc], v);
        }
    }
}

// =====================================================================
// launch
// =====================================================================
extern "C" void kernel_launch(void* const* d_in, const int* in_sizes, int n_in,
                              void* d_out, int out_size)
{
    const float* x     = (const float*)d_in[1];
    const float* W     = (const float*)d_in[2];
    const float* a_src = (const float*)d_in[3];
    const float* a_dst = (const float*)d_in[4];
    const float* W1    = (const float*)d_in[5];
    const float* b1    = (const float*)d_in[6];
    const float* W2    = (const float*)d_in[7];
    const float* b2    = (const float*)d_in[8];
    float* out = (float*)d_out;

    const int batch = in_sizes[1] / KDIM;   // 16384

    cudaFuncSetAttribute(gat_tc, cudaFuncAttributeMaxDynamicSharedMemorySize, GAT_SMEM);
    cudaFuncSetAttribute(mlp_mma, cudaFuncAttributeMaxDynamicSharedMemorySize, MLP_SMEM);

    const int prep_total = 256 * KPAD + 12 * 32 * 40 + 12 * 32;
    prep_all<<<(prep_total + 255) / 256, 256>>>(W1, W, a_src, a_dst);
    zero_out<<<(batch * 3 + 255) / 256, 256>>>(out, batch * 3);
    gat_tc<<<batch / 8, 256, GAT_SMEM>>>(x);
    dim3 mgrid(batch / 64, 2);
    mlp_mma<<<mgrid, 256, MLP_SMEM>>>(b1, W2, b2, out);
    (void)n_in; (void)out_size;
}